// round 2
// baseline (speedup 1.0000x reference)
#include <cuda_runtime.h>
#include <cuda_bf16.h>
#include <cstdint>

#define HID 256
#define HID4 (HID/4)
#define MAX_N 50000
#define MAX_E 800000

// ---------------- scratch (static __device__, no allocs) ----------------
__device__ float g_w[MAX_E];              // per-edge sigmoid weight
__device__ float g_dinv[MAX_N];           // degree, then rsqrt(degree)
__device__ float g_x[(size_t)MAX_N * HID];// h @ Wc

// ---------------- kernel 1: edge MLP -> w ----------------
__global__ void edge_mlp_kernel(const float* __restrict__ attr,
                                const float* __restrict__ W1,
                                const float* __restrict__ b1,
                                const float* __restrict__ W2,
                                const float* __restrict__ b2,
                                float* __restrict__ w, int E) {
    __shared__ float sW1[3 * 128];
    __shared__ float sb1[128];
    __shared__ float sW2[128];
    for (int i = threadIdx.x; i < 384; i += blockDim.x) sW1[i] = W1[i];
    for (int i = threadIdx.x; i < 128; i += blockDim.x) { sb1[i] = b1[i]; sW2[i] = W2[i]; }
    __syncthreads();
    int e = blockIdx.x * blockDim.x + threadIdx.x;
    if (e >= E) return;
    float a0 = attr[e * 3 + 0];
    float a1 = attr[e * 3 + 1];
    float a2 = attr[e * 3 + 2];
    float acc = 0.0f;
#pragma unroll 8
    for (int j = 0; j < 128; j++) {
        float z = fmaf(a0, sW1[j], fmaf(a1, sW1[128 + j], fmaf(a2, sW1[256 + j], sb1[j])));
        // silu(z) = z * sigmoid(z)
        float sg = 1.0f / (1.0f + expf(-z));
        acc = fmaf(z * sg, sW2[j], acc);
    }
    float zz = acc + b2[0];
    w[e] = 1.0f / (1.0f + expf(-zz));
}

// ---------------- kernel 2: degree ----------------
__global__ void deg_init_kernel(float* __restrict__ deg, int N) {
    int i = blockIdx.x * blockDim.x + threadIdx.x;
    if (i < N) deg[i] = 1.0f;   // self-loop weight
}

__global__ void deg_acc_kernel(const int* __restrict__ dst,
                               const float* __restrict__ w,
                               float* __restrict__ deg, int E) {
    int e = blockIdx.x * blockDim.x + threadIdx.x;
    if (e < E) atomicAdd(&deg[dst[e]], w[e]);
}

__global__ void deg_finish_kernel(float* __restrict__ deg, int N) {
    int i = blockIdx.x * blockDim.x + threadIdx.x;
    if (i < N) deg[i] = rsqrtf(deg[i]);  // deg >= 1 always (self loop)
}

// ---------------- kernel 3: SGEMM  x = h @ Wc  (M x 256 @ 256 x 256) ----------------
#define BM 128
#define BN 128
#define BK 16
#define TM 8
#define TN 8
__global__ __launch_bounds__(256) void sgemm_kernel(const float* __restrict__ A,
                                                    const float* __restrict__ B,
                                                    float* __restrict__ C, int M) {
    const int K = HID, N = HID;
    __shared__ float As[BK][BM];
    __shared__ float Bs[BK][BN];
    int tid = threadIdx.x;
    int block_m = blockIdx.x * BM;
    int block_n = blockIdx.y * BN;
    int tr = tid / (BN / TN);   // 0..15
    int tc = tid % (BN / TN);   // 0..15
    float acc[TM][TN];
#pragma unroll
    for (int i = 0; i < TM; i++)
#pragma unroll
        for (int j = 0; j < TN; j++) acc[i][j] = 0.0f;

    int aRow = tid / (BK / 4);          // 0..63
    int aCol = (tid % (BK / 4)) * 4;    // 0,4,8,12
    int bRow = tid / (BN / 4);          // 0..7
    int bCol = (tid % (BN / 4)) * 4;    // 0..124

    for (int k0 = 0; k0 < K; k0 += BK) {
#pragma unroll
        for (int i = 0; i < 2; i++) {
            int m = block_m + aRow + i * 64;
            float4 v = make_float4(0.f, 0.f, 0.f, 0.f);
            if (m < M) v = *(const float4*)&A[(size_t)m * K + k0 + aCol];
            As[aCol + 0][aRow + i * 64] = v.x;
            As[aCol + 1][aRow + i * 64] = v.y;
            As[aCol + 2][aRow + i * 64] = v.z;
            As[aCol + 3][aRow + i * 64] = v.w;
        }
#pragma unroll
        for (int j = 0; j < 2; j++) {
            *(float4*)&Bs[bRow + j * 8][bCol] =
                *(const float4*)&B[(size_t)(k0 + bRow + j * 8) * N + block_n + bCol];
        }
        __syncthreads();
#pragma unroll
        for (int kk = 0; kk < BK; kk++) {
            float ra[TM], rb[TN];
#pragma unroll
            for (int i = 0; i < TM; i++) ra[i] = As[kk][tr * TM + i];
#pragma unroll
            for (int j = 0; j < TN; j++) rb[j] = Bs[kk][tc * TN + j];
#pragma unroll
            for (int i = 0; i < TM; i++)
#pragma unroll
                for (int j = 0; j < TN; j++) acc[i][j] = fmaf(ra[i], rb[j], acc[i][j]);
        }
        __syncthreads();
    }
#pragma unroll
    for (int i = 0; i < TM; i++) {
        int m = block_m + tr * TM + i;
        if (m < M) {
#pragma unroll
            for (int j = 0; j < TN; j += 4) {
                float4 v = make_float4(acc[i][j], acc[i][j + 1], acc[i][j + 2], acc[i][j + 3]);
                *(float4*)&C[(size_t)m * N + block_n + tc * TN + j] = v;
            }
        }
    }
}

// ---------------- kernel 4: init out with bias + self-loop term ----------------
__global__ void init_out_kernel(const float* __restrict__ x,
                                const float* __restrict__ dinv,
                                const float* __restrict__ bc,
                                float* __restrict__ out, int N) {
    int idx = blockIdx.x * blockDim.x + threadIdx.x;  // over N * HID4
    if (idx >= N * HID4) return;
    int node = idx >> 6;      // /HID4
    int c4 = idx & (HID4 - 1);
    float d = dinv[node];
    float s = d * d;          // self-loop norm: dinv*1*dinv
    float4 xv = ((const float4*)x)[idx];
    float4 bv = ((const float4*)bc)[c4];
    float4 o;
    o.x = fmaf(s, xv.x, bv.x);
    o.y = fmaf(s, xv.y, bv.y);
    o.z = fmaf(s, xv.z, bv.z);
    o.w = fmaf(s, xv.w, bv.w);
    ((float4*)out)[idx] = o;
}

// ---------------- kernel 5: edge aggregation (1 warp / edge, red.v4) ----------------
__device__ __forceinline__ void red_add_v4(float* addr, float4 v) {
    asm volatile("red.global.add.v4.f32 [%0], {%1,%2,%3,%4};"
                 :: "l"(addr), "f"(v.x), "f"(v.y), "f"(v.z), "f"(v.w)
                 : "memory");
}

__global__ __launch_bounds__(256) void agg_kernel(const int* __restrict__ src,
                                                  const int* __restrict__ dst,
                                                  const float* __restrict__ w,
                                                  const float* __restrict__ dinv,
                                                  const float* __restrict__ x,
                                                  float* __restrict__ out, int E) {
    int warp = (blockIdx.x * blockDim.x + threadIdx.x) >> 5;
    int lane = threadIdx.x & 31;
    if (warp >= E) return;
    int r = src[warp];
    int c = dst[warp];
    float nrm = w[warp] * dinv[r] * dinv[c];
    const float4* xr = (const float4*)(x + (size_t)r * HID);
    float* oc = out + (size_t)c * HID;
#pragma unroll
    for (int i = 0; i < 2; i++) {
        int k = lane + i * 32;               // 0..63 float4 chunks
        float4 v = xr[k];
        v.x *= nrm; v.y *= nrm; v.z *= nrm; v.w *= nrm;
        red_add_v4(oc + k * 4, v);
    }
}

// ---------------- launcher ----------------
extern "C" void kernel_launch(void* const* d_in, const int* in_sizes, int n_in,
                              void* d_out, int out_size) {
    const float* h    = (const float*)d_in[0];
    const int*   eidx = (const int*)d_in[1];     // JAX int64 request -> int32 (x64 disabled)
    const float* attr = (const float*)d_in[2];
    const float* W1   = (const float*)d_in[3];
    const float* b1   = (const float*)d_in[4];
    const float* W2   = (const float*)d_in[5];
    const float* b2   = (const float*)d_in[6];
    const float* Wc   = (const float*)d_in[7];
    const float* bc   = (const float*)d_in[8];
    float* out = (float*)d_out;

    int N = in_sizes[0] / HID;       // 50000
    int E = in_sizes[2] / 3;         // 800000
    const int* src = eidx;           // edge_index[0] (sources)
    const int* dst = eidx + E;       // edge_index[1] (targets)

    float* w_dev;    cudaGetSymbolAddress((void**)&w_dev, g_w);
    float* dinv_dev; cudaGetSymbolAddress((void**)&dinv_dev, g_dinv);
    float* x_dev;    cudaGetSymbolAddress((void**)&x_dev, g_x);

    // 1. edge weights
    edge_mlp_kernel<<<(E + 255) / 256, 256>>>(attr, W1, b1, W2, b2, w_dev, E);
    // 2. degree -> dinv
    deg_init_kernel<<<(N + 255) / 256, 256>>>(dinv_dev, N);
    deg_acc_kernel<<<(E + 255) / 256, 256>>>(dst, w_dev, dinv_dev, E);
    deg_finish_kernel<<<(N + 255) / 256, 256>>>(dinv_dev, N);
    // 3. x = h @ Wc
    dim3 ggrid((N + BM - 1) / BM, HID / BN);
    sgemm_kernel<<<ggrid, 256>>>(h, Wc, x_dev, N);
    // 4. out = bc + dinv^2 * x   (self loop)
    int tot = N * HID4;
    init_out_kernel<<<(tot + 255) / 256, 256>>>(x_dev, dinv_dev, bc, out, N);
    // 5. scatter edges
    long long tthreads = (long long)E * 32;
    agg_kernel<<<(unsigned)((tthreads + 255) / 256), 256>>>(src, dst, w_dev, dinv_dev, x_dev, out, E);
}

// round 3
// speedup vs baseline: 1.0291x; 1.0291x over previous
#include <cuda_runtime.h>
#include <cuda_bf16.h>
#include <cstdint>

#define HID 256
#define MAX_N 50000
#define MAX_E 800000
#define SCAN_T 1024

// ---------------- scratch (static __device__, no allocs) ----------------
__device__ float g_w[MAX_E];                 // per-edge sigmoid weight
__device__ float g_dinv[MAX_N];              // degree -> rsqrt(degree)
__device__ float g_x[(size_t)MAX_N * HID];   // h @ Wc
__device__ int   g_cnt[MAX_N];               // per-dst edge count
__device__ int   g_ptr[MAX_N + 1];           // CSR offsets
__device__ int   g_cur[MAX_N];               // scatter cursors
__device__ int   g_esrc[MAX_E];              // sorted edge sources
__device__ float g_enrm[MAX_E];              // sorted edge norms

// ---------------- helpers ----------------
__device__ __forceinline__ float tanh_approx(float x) {
    float r;
    asm("tanh.approx.f32 %0, %1;" : "=f"(r) : "f"(x));
    return r;
}
__device__ __forceinline__ float to_tf32(float x) {
    uint32_t u;
    asm("cvt.rna.tf32.f32 %0, %1;" : "=r"(u) : "f"(x));
    return __uint_as_float(u);
}
__device__ __forceinline__ void mma_tf32(float4& c, const uint32_t* a, const uint32_t* b) {
    asm volatile(
        "mma.sync.aligned.m16n8k8.row.col.f32.tf32.tf32.f32 "
        "{%0,%1,%2,%3},{%4,%5,%6,%7},{%8,%9},{%0,%1,%2,%3};"
        : "+f"(c.x), "+f"(c.y), "+f"(c.z), "+f"(c.w)
        : "r"(a[0]), "r"(a[1]), "r"(a[2]), "r"(a[3]), "r"(b[0]), "r"(b[1]));
}

// ---------------- kernel 1: edge MLP -> w ----------------
__global__ __launch_bounds__(256) void edge_mlp_kernel(const float* __restrict__ attr,
                                const float* __restrict__ W1,
                                const float* __restrict__ b1,
                                const float* __restrict__ W2,
                                const float* __restrict__ b2,
                                float* __restrict__ w, int E) {
    __shared__ float4 sA[128];   // {W1[0][j], W1[1][j], W1[2][j], b1[j]}
    __shared__ float  sV[128];   // W2[j]
    for (int j = threadIdx.x; j < 128; j += blockDim.x) {
        sA[j] = make_float4(W1[j], W1[128 + j], W1[256 + j], b1[j]);
        sV[j] = W2[j];
    }
    __syncthreads();
    int e = blockIdx.x * blockDim.x + threadIdx.x;
    if (e >= E) return;
    float a0 = attr[e * 3 + 0];
    float a1 = attr[e * 3 + 1];
    float a2 = attr[e * 3 + 2];
    float acc = b2[0];
#pragma unroll 8
    for (int j = 0; j < 128; j++) {
        float4 c = sA[j];
        float z = fmaf(a0, c.x, fmaf(a1, c.y, fmaf(a2, c.z, c.w)));
        // silu(z) = z * sigmoid(z) = 0.5*z*(1 + tanh(z/2))
        float t = tanh_approx(0.5f * z);
        float silu = 0.5f * z * (1.0f + t);
        acc = fmaf(silu, sV[j], acc);
    }
    // sigmoid(acc)
    w[e] = fmaf(0.5f, tanh_approx(0.5f * acc), 0.5f);
}

// ---------------- kernel 2: degree + histogram ----------------
__global__ void deg_init_kernel(float* __restrict__ deg, int N) {
    int i = blockIdx.x * blockDim.x + threadIdx.x;
    if (i < N) deg[i] = 1.0f;   // self-loop weight
}

__global__ void deg_cnt_kernel(const int* __restrict__ dst,
                               const float* __restrict__ w,
                               float* __restrict__ deg,
                               int* __restrict__ cnt, int E) {
    int e = blockIdx.x * blockDim.x + threadIdx.x;
    if (e < E) {
        int c = dst[e];
        atomicAdd(&deg[c], w[e]);
        atomicAdd(&cnt[c], 1);
    }
}

__global__ void deg_finish_kernel(float* __restrict__ deg, int N) {
    int i = blockIdx.x * blockDim.x + threadIdx.x;
    if (i < N) deg[i] = rsqrtf(deg[i]);  // deg >= 1 always (self loop)
}

// ---------------- kernel 3: exclusive scan (single block) ----------------
__global__ __launch_bounds__(SCAN_T) void scan_kernel(const int* __restrict__ cnt,
                                                      int* __restrict__ ptr,
                                                      int* __restrict__ cur, int N) {
    __shared__ int ssum[SCAN_T];
    int tid = threadIdx.x;
    int CH = (N + SCAN_T - 1) / SCAN_T;
    int start = tid * CH;
    int local = 0;
    for (int i = 0; i < CH; i++) {
        int idx = start + i;
        if (idx < N) local += cnt[idx];
    }
    ssum[tid] = local;
    __syncthreads();
    for (int off = 1; off < SCAN_T; off <<= 1) {
        int v = (tid >= off) ? ssum[tid - off] : 0;
        __syncthreads();
        ssum[tid] += v;
        __syncthreads();
    }
    int run = ssum[tid] - local;  // exclusive base for this chunk
    for (int i = 0; i < CH; i++) {
        int idx = start + i;
        if (idx < N) {
            ptr[idx] = run;
            cur[idx] = run;
            run += cnt[idx];
        }
    }
    if (tid == SCAN_T - 1) ptr[N] = ssum[SCAN_T - 1];
}

// ---------------- kernel 4: scatter edges into CSR ----------------
__global__ void scatter_kernel(const int* __restrict__ src,
                               const int* __restrict__ dst,
                               const float* __restrict__ w,
                               const float* __restrict__ dinv,
                               int* __restrict__ cur,
                               int* __restrict__ esrc,
                               float* __restrict__ enrm, int E) {
    int e = blockIdx.x * blockDim.x + threadIdx.x;
    if (e >= E) return;
    int r = src[e];
    int c = dst[e];
    float nrm = w[e] * dinv[r] * dinv[c];
    int pos = atomicAdd(&cur[c], 1);
    esrc[pos] = r;
    enrm[pos] = nrm;
}

// ---------------- kernel 5: TF32 tensor-core GEMM  x = h @ Wc ----------------
// CTA tile 128x128, 8 warps, warp tile 32x64, BK=32, K=N=256 fixed.
#define GBM 128
#define GBN 128
#define GBK 32
__global__ __launch_bounds__(256) void tf32_gemm_kernel(const float* __restrict__ A,
                                                        const float* __restrict__ B,
                                                        float* __restrict__ C, int M) {
    __shared__ float As[GBK][GBM + 4];   // [k][m]  tf32 values
    __shared__ float Bs[GBK][GBN + 4];   // [k][n]  tf32 values

    int tid = threadIdx.x;
    int wid = tid >> 5;
    int lane = tid & 31;
    int g = lane >> 2;       // 0..7
    int tig = lane & 3;      // 0..3
    int bm = blockIdx.x * GBM;
    int bn = blockIdx.y * GBN;
    int wm = (wid >> 1) * 32;    // 0,32,64,96
    int wn = (wid & 1) * 64;     // 0,64

    float4 acc[2][8];
#pragma unroll
    for (int mt = 0; mt < 2; mt++)
#pragma unroll
        for (int j = 0; j < 8; j++) acc[mt][j] = make_float4(0.f, 0.f, 0.f, 0.f);

    int arow = tid >> 3;          // 0..31
    int acol4 = tid & 7;          // 0..7 (float4 col)
    int brow = tid >> 5;          // 0..7
    int bcol4 = tid & 31;         // 0..31 (float4 col)

    for (int k0 = 0; k0 < HID; k0 += GBK) {
        // load A tile (transposed into As[k][m]) with tf32 rounding
#pragma unroll
        for (int i = 0; i < 4; i++) {
            int m = arow + 32 * i;
            int gr = bm + m;
            float4 v = make_float4(0.f, 0.f, 0.f, 0.f);
            if (gr < M) v = *(const float4*)&A[(size_t)gr * HID + k0 + acol4 * 4];
            As[acol4 * 4 + 0][m] = to_tf32(v.x);
            As[acol4 * 4 + 1][m] = to_tf32(v.y);
            As[acol4 * 4 + 2][m] = to_tf32(v.z);
            As[acol4 * 4 + 3][m] = to_tf32(v.w);
        }
        // load B tile into Bs[k][n]
#pragma unroll
        for (int i = 0; i < 4; i++) {
            int kk = brow + 8 * i;
            float4 v = *(const float4*)&B[(size_t)(k0 + kk) * HID + bn + bcol4 * 4];
            v.x = to_tf32(v.x); v.y = to_tf32(v.y); v.z = to_tf32(v.z); v.w = to_tf32(v.w);
            *(float4*)&Bs[kk][bcol4 * 4] = v;
        }
        __syncthreads();

#pragma unroll
        for (int kr = 0; kr < GBK; kr += 8) {
            uint32_t af[2][4];
            uint32_t bf[8][2];
#pragma unroll
            for (int mt = 0; mt < 2; mt++) {
                int mb = wm + mt * 16 + g;
                af[mt][0] = __float_as_uint(As[kr + tig][mb]);
                af[mt][1] = __float_as_uint(As[kr + tig][mb + 8]);
                af[mt][2] = __float_as_uint(As[kr + tig + 4][mb]);
                af[mt][3] = __float_as_uint(As[kr + tig + 4][mb + 8]);
            }
#pragma unroll
            for (int j = 0; j < 8; j++) {
                int nb = wn + j * 8 + g;
                bf[j][0] = __float_as_uint(Bs[kr + tig][nb]);
                bf[j][1] = __float_as_uint(Bs[kr + tig + 4][nb]);
            }
#pragma unroll
            for (int mt = 0; mt < 2; mt++)
#pragma unroll
                for (int j = 0; j < 8; j++)
                    mma_tf32(acc[mt][j], af[mt], bf[j]);
        }
        __syncthreads();
    }

    // store C
#pragma unroll
    for (int mt = 0; mt < 2; mt++) {
        int row0 = bm + wm + mt * 16 + g;
        int row1 = row0 + 8;
#pragma unroll
        for (int j = 0; j < 8; j++) {
            int col = bn + wn + j * 8 + tig * 2;
            if (row0 < M) *(float2*)&C[(size_t)row0 * HID + col] = make_float2(acc[mt][j].x, acc[mt][j].y);
            if (row1 < M) *(float2*)&C[(size_t)row1 * HID + col] = make_float2(acc[mt][j].z, acc[mt][j].w);
        }
    }
}

// ---------------- kernel 6: pull aggregation (1 warp / node) ----------------
__global__ __launch_bounds__(256) void agg_pull_kernel(const int* __restrict__ ptr,
                                                       const int* __restrict__ esrc,
                                                       const float* __restrict__ enrm,
                                                       const float* __restrict__ dinv,
                                                       const float* __restrict__ x,
                                                       const float* __restrict__ bc,
                                                       float* __restrict__ out, int N) {
    int node = (blockIdx.x * blockDim.x + threadIdx.x) >> 5;
    int lane = threadIdx.x & 31;
    if (node >= N) return;
    const float4* x4 = (const float4*)x;
    const float4* bc4 = (const float4*)bc;
    float4* out4 = (float4*)out;

    float d = dinv[node];
    float s = d * d;   // self-loop norm
    size_t base = (size_t)node * 64;
    float4 xa = x4[base + lane];
    float4 xb = x4[base + lane + 32];
    float4 ba = bc4[lane];
    float4 bb = bc4[lane + 32];
    float4 acc0, acc1;
    acc0.x = fmaf(s, xa.x, ba.x); acc0.y = fmaf(s, xa.y, ba.y);
    acc0.z = fmaf(s, xa.z, ba.z); acc0.w = fmaf(s, xa.w, ba.w);
    acc1.x = fmaf(s, xb.x, bb.x); acc1.y = fmaf(s, xb.y, bb.y);
    acc1.z = fmaf(s, xb.z, bb.z); acc1.w = fmaf(s, xb.w, bb.w);

    int i = ptr[node];
    int end = ptr[node + 1];
    int r = 0; float nm = 0.f;
    if (i < end) { r = esrc[i]; nm = enrm[i]; }
    while (i < end) {
        int in = i + 1;
        int rn = 0; float nmn = 0.f;
        if (in < end) { rn = esrc[in]; nmn = enrm[in]; }  // prefetch next
        size_t rb = (size_t)r * 64;
        float4 va = x4[rb + lane];
        float4 vb = x4[rb + lane + 32];
        acc0.x = fmaf(nm, va.x, acc0.x); acc0.y = fmaf(nm, va.y, acc0.y);
        acc0.z = fmaf(nm, va.z, acc0.z); acc0.w = fmaf(nm, va.w, acc0.w);
        acc1.x = fmaf(nm, vb.x, acc1.x); acc1.y = fmaf(nm, vb.y, acc1.y);
        acc1.z = fmaf(nm, vb.z, acc1.z); acc1.w = fmaf(nm, vb.w, acc1.w);
        r = rn; nm = nmn; i = in;
    }
    out4[base + lane] = acc0;
    out4[base + lane + 32] = acc1;
}

// ---------------- launcher ----------------
extern "C" void kernel_launch(void* const* d_in, const int* in_sizes, int n_in,
                              void* d_out, int out_size) {
    const float* h    = (const float*)d_in[0];
    const int*   eidx = (const int*)d_in[1];     // JAX int64 -> int32 (x64 disabled)
    const float* attr = (const float*)d_in[2];
    const float* W1   = (const float*)d_in[3];
    const float* b1   = (const float*)d_in[4];
    const float* W2   = (const float*)d_in[5];
    const float* b2   = (const float*)d_in[6];
    const float* Wc   = (const float*)d_in[7];
    const float* bc   = (const float*)d_in[8];
    float* out = (float*)d_out;

    int N = in_sizes[0] / HID;       // 50000
    int E = in_sizes[2] / 3;         // 800000
    const int* src = eidx;           // edge_index[0] (sources)
    const int* dst = eidx + E;       // edge_index[1] (targets)

    float* w_dev;    cudaGetSymbolAddress((void**)&w_dev, g_w);
    float* dinv_dev; cudaGetSymbolAddress((void**)&dinv_dev, g_dinv);
    float* x_dev;    cudaGetSymbolAddress((void**)&x_dev, g_x);
    int*   cnt_dev;  cudaGetSymbolAddress((void**)&cnt_dev, g_cnt);
    int*   ptr_dev;  cudaGetSymbolAddress((void**)&ptr_dev, g_ptr);
    int*   cur_dev;  cudaGetSymbolAddress((void**)&cur_dev, g_cur);
    int*   esrc_dev; cudaGetSymbolAddress((void**)&esrc_dev, g_esrc);
    float* enrm_dev; cudaGetSymbolAddress((void**)&enrm_dev, g_enrm);

    int eb = (E + 255) / 256;
    int nb = (N + 255) / 256;

    // 1. edge weights
    edge_mlp_kernel<<<eb, 256>>>(attr, W1, b1, W2, b2, w_dev, E);
    // 2. degree + histogram
    deg_init_kernel<<<nb, 256>>>(dinv_dev, N);
    cudaMemsetAsync(cnt_dev, 0, (size_t)N * sizeof(int));
    deg_cnt_kernel<<<eb, 256>>>(dst, w_dev, dinv_dev, cnt_dev, E);
    deg_finish_kernel<<<nb, 256>>>(dinv_dev, N);
    // 3. CSR build
    scan_kernel<<<1, SCAN_T>>>(cnt_dev, ptr_dev, cur_dev, N);
    scatter_kernel<<<eb, 256>>>(src, dst, w_dev, dinv_dev, cur_dev, esrc_dev, enrm_dev, E);
    // 4. x = h @ Wc (tf32 tensor cores)
    dim3 ggrid((N + GBM - 1) / GBM, HID / GBN);
    tf32_gemm_kernel<<<ggrid, 256>>>(h, Wc, x_dev, N);
    // 5. pull aggregation (fused bias + self loop)
    int ab = (N * 32 + 255) / 256;
    agg_pull_kernel<<<ab, 256>>>(ptr_dev, esrc_dev, enrm_dev, dinv_dev, x_dev, bc, out, N);
}

// round 5
// speedup vs baseline: 1.5849x; 1.5401x over previous
#include <cuda_runtime.h>
#include <cuda_bf16.h>
#include <cstdint>

#define HID 256
#define MAX_N 50000
#define MAX_E 800000

// ---------------- scratch (static __device__, no allocs) ----------------
__device__ float g_w[MAX_E];                 // per-edge sigmoid weight
__device__ float g_deg[MAX_N];               // weighted degree (excl. self loop)
__device__ float g_dinv[MAX_N];              // rsqrt(deg+1)
__device__ float g_x[(size_t)MAX_N * HID];   // h @ Wc

// ---------------- helpers ----------------
__device__ __forceinline__ float tanh_approx(float x) {
    float r;
    asm("tanh.approx.f32 %0, %1;" : "=f"(r) : "f"(x));
    return r;
}
__device__ __forceinline__ float to_tf32(float x) {
    uint32_t u;
    asm("cvt.rna.tf32.f32 %0, %1;" : "=r"(u) : "f"(x));
    return __uint_as_float(u);
}
__device__ __forceinline__ void mma_tf32(float4& c, const uint32_t* a, const uint32_t* b) {
    asm volatile(
        "mma.sync.aligned.m16n8k8.row.col.f32.tf32.tf32.f32 "
        "{%0,%1,%2,%3},{%4,%5,%6,%7},{%8,%9},{%0,%1,%2,%3};"
        : "+f"(c.x), "+f"(c.y), "+f"(c.z), "+f"(c.w)
        : "r"(a[0]), "r"(a[1]), "r"(a[2]), "r"(a[3]), "r"(b[0]), "r"(b[1]));
}
__device__ __forceinline__ void red_add_v4(float* addr, float4 v) {
    asm volatile("red.global.add.v4.f32 [%0], {%1,%2,%3,%4};"
                 :: "l"(addr), "f"(v.x), "f"(v.y), "f"(v.z), "f"(v.w)
                 : "memory");
}

// ---------------- kernel 1: TF32 tensor-core GEMM  x = h @ Wc ----------------
// CTA tile 128x128, 8 warps, warp tile 32x64, BK=32, K=N=256 fixed.
#define GBM 128
#define GBN 128
#define GBK 32
__global__ __launch_bounds__(256) void tf32_gemm_kernel(const float* __restrict__ A,
                                                        const float* __restrict__ B,
                                                        float* __restrict__ C, int M) {
    __shared__ float As[GBK][GBM + 4];   // [k][m]
    __shared__ float Bs[GBK][GBN + 4];   // [k][n]

    int tid = threadIdx.x;
    int wid = tid >> 5;
    int lane = tid & 31;
    int g = lane >> 2;       // 0..7
    int tig = lane & 3;      // 0..3
    int bm = blockIdx.x * GBM;
    int bn = blockIdx.y * GBN;
    int wm = (wid >> 1) * 32;    // 0,32,64,96
    int wn = (wid & 1) * 64;     // 0,64

    float4 acc[2][8];
#pragma unroll
    for (int mt = 0; mt < 2; mt++)
#pragma unroll
        for (int j = 0; j < 8; j++) acc[mt][j] = make_float4(0.f, 0.f, 0.f, 0.f);

    int arow = tid >> 3;          // 0..31
    int acol4 = tid & 7;          // 0..7
    int brow = tid >> 5;          // 0..7
    int bcol4 = tid & 31;         // 0..31

    for (int k0 = 0; k0 < HID; k0 += GBK) {
#pragma unroll
        for (int i = 0; i < 4; i++) {
            int m = arow + 32 * i;
            int gr = bm + m;
            float4 v = make_float4(0.f, 0.f, 0.f, 0.f);
            if (gr < M) v = *(const float4*)&A[(size_t)gr * HID + k0 + acol4 * 4];
            As[acol4 * 4 + 0][m] = to_tf32(v.x);
            As[acol4 * 4 + 1][m] = to_tf32(v.y);
            As[acol4 * 4 + 2][m] = to_tf32(v.z);
            As[acol4 * 4 + 3][m] = to_tf32(v.w);
        }
#pragma unroll
        for (int i = 0; i < 4; i++) {
            int kk = brow + 8 * i;
            float4 v = *(const float4*)&B[(size_t)(k0 + kk) * HID + bn + bcol4 * 4];
            v.x = to_tf32(v.x); v.y = to_tf32(v.y); v.z = to_tf32(v.z); v.w = to_tf32(v.w);
            *(float4*)&Bs[kk][bcol4 * 4] = v;
        }
        __syncthreads();

#pragma unroll
        for (int kr = 0; kr < GBK; kr += 8) {
            uint32_t af[2][4];
            uint32_t bf[8][2];
#pragma unroll
            for (int mt = 0; mt < 2; mt++) {
                int mb = wm + mt * 16 + g;
                af[mt][0] = __float_as_uint(As[kr + tig][mb]);
                af[mt][1] = __float_as_uint(As[kr + tig][mb + 8]);
                af[mt][2] = __float_as_uint(As[kr + tig + 4][mb]);
                af[mt][3] = __float_as_uint(As[kr + tig + 4][mb + 8]);
            }
#pragma unroll
            for (int j = 0; j < 8; j++) {
                int nb = wn + j * 8 + g;
                bf[j][0] = __float_as_uint(Bs[kr + tig][nb]);
                bf[j][1] = __float_as_uint(Bs[kr + tig + 4][nb]);
            }
#pragma unroll
            for (int mt = 0; mt < 2; mt++)
#pragma unroll
                for (int j = 0; j < 8; j++)
                    mma_tf32(acc[mt][j], af[mt], bf[j]);
        }
        __syncthreads();
    }

#pragma unroll
    for (int mt = 0; mt < 2; mt++) {
        int row0 = bm + wm + mt * 16 + g;
        int row1 = row0 + 8;
#pragma unroll
        for (int j = 0; j < 8; j++) {
            int col = bn + wn + j * 8 + tig * 2;
            if (row0 < M) *(float2*)&C[(size_t)row0 * HID + col] = make_float2(acc[mt][j].x, acc[mt][j].y);
            if (row1 < M) *(float2*)&C[(size_t)row1 * HID + col] = make_float2(acc[mt][j].z, acc[mt][j].w);
        }
    }
}

// ---------------- kernel 2: fused edge MLP -> w, + weighted degree ----------------
__global__ __launch_bounds__(256) void fused_edge_kernel(const float* __restrict__ attr,
                                const float* __restrict__ W1,
                                const float* __restrict__ b1,
                                const float* __restrict__ W2,
                                const float* __restrict__ b2,
                                const int* __restrict__ dst,
                                float* __restrict__ w,
                                float* __restrict__ deg, int E) {
    __shared__ float4 sA[128];   // {W1[0][j], W1[1][j], W1[2][j], b1[j]}
    __shared__ float  sV[128];   // W2[j]
    for (int j = threadIdx.x; j < 128; j += blockDim.x) {
        sA[j] = make_float4(W1[j], W1[128 + j], W1[256 + j], b1[j]);
        sV[j] = W2[j];
    }
    __syncthreads();
    int e = blockIdx.x * blockDim.x + threadIdx.x;
    if (e >= E) return;
    float a0 = attr[e * 3 + 0];
    float a1 = attr[e * 3 + 1];
    float a2 = attr[e * 3 + 2];
    float acc = b2[0];
#pragma unroll 8
    for (int j = 0; j < 128; j++) {
        float4 c = sA[j];
        float z = fmaf(a0, c.x, fmaf(a1, c.y, fmaf(a2, c.z, c.w)));
        float t = tanh_approx(0.5f * z);            // silu via tanh
        acc = fmaf(0.5f * z * (1.0f + t), sV[j], acc);
    }
    float wv = fmaf(0.5f, tanh_approx(0.5f * acc), 0.5f);  // sigmoid
    w[e] = wv;
    atomicAdd(&deg[dst[e]], wv);
}

// ---------------- kernel 3: dinv + out init (bias + self loop), 1 warp/node ----------------
__global__ __launch_bounds__(256) void finish_init_kernel(const float* __restrict__ deg,
                                                          float* __restrict__ dinv,
                                                          const float* __restrict__ x,
                                                          const float* __restrict__ bc,
                                                          float* __restrict__ out, int N) {
    int node = (blockIdx.x * blockDim.x + threadIdx.x) >> 5;
    int lane = threadIdx.x & 31;
    if (node >= N) return;
    float d = rsqrtf(deg[node] + 1.0f);   // + self loop weight
    if (lane == 0) dinv[node] = d;
    float s = d * d;
    const float4* x4 = (const float4*)x;
    const float4* bc4 = (const float4*)bc;
    float4* out4 = (float4*)out;
    size_t base = (size_t)node * 64;
#pragma unroll
    for (int i = 0; i < 2; i++) {
        int k = lane + i * 32;
        float4 xv = x4[base + k];
        float4 bv = bc4[k];
        float4 o;
        o.x = fmaf(s, xv.x, bv.x);
        o.y = fmaf(s, xv.y, bv.y);
        o.z = fmaf(s, xv.z, bv.z);
        o.w = fmaf(s, xv.w, bv.w);
        out4[base + k] = o;
    }
}

// ---------------- kernel 4: edge aggregation (1 warp / edge, red.v4) ----------------
__global__ __launch_bounds__(256) void agg_kernel(const int* __restrict__ src,
                                                  const int* __restrict__ dst,
                                                  const float* __restrict__ w,
                                                  const float* __restrict__ dinv,
                                                  const float* __restrict__ x,
                                                  float* __restrict__ out, int E) {
    int warp = (blockIdx.x * blockDim.x + threadIdx.x) >> 5;
    int lane = threadIdx.x & 31;
    if (warp >= E) return;
    int r = src[warp];
    int c = dst[warp];
    float nrm = w[warp] * dinv[r] * dinv[c];
    const float4* xr = (const float4*)(x + (size_t)r * HID);
    float* oc = out + (size_t)c * HID;
#pragma unroll
    for (int i = 0; i < 2; i++) {
        int k = lane + i * 32;               // 0..63 float4 chunks
        float4 v = xr[k];
        v.x *= nrm; v.y *= nrm; v.z *= nrm; v.w *= nrm;
        red_add_v4(oc + k * 4, v);
    }
}

// ---------------- launcher ----------------
extern "C" void kernel_launch(void* const* d_in, const int* in_sizes, int n_in,
                              void* d_out, int out_size) {
    const float* h    = (const float*)d_in[0];
    const int*   eidx = (const int*)d_in[1];     // JAX int64 -> int32 (x64 disabled)
    const float* attr = (const float*)d_in[2];
    const float* W1   = (const float*)d_in[3];
    const float* b1   = (const float*)d_in[4];
    const float* W2   = (const float*)d_in[5];
    const float* b2   = (const float*)d_in[6];
    const float* Wc   = (const float*)d_in[7];
    const float* bc   = (const float*)d_in[8];
    float* out = (float*)d_out;

    int N = in_sizes[0] / HID;       // 50000
    int E = in_sizes[2] / 3;         // 800000
    const int* src = eidx;           // edge_index[0] (sources)
    const int* dst = eidx + E;       // edge_index[1] (targets)

    float* w_dev;    cudaGetSymbolAddress((void**)&w_dev, g_w);
    float* deg_dev;  cudaGetSymbolAddress((void**)&deg_dev, g_deg);
    float* dinv_dev; cudaGetSymbolAddress((void**)&dinv_dev, g_dinv);
    float* x_dev;    cudaGetSymbolAddress((void**)&x_dev, g_x);

    cudaMemsetAsync(deg_dev, 0, (size_t)N * sizeof(float));

    // 1. x = h @ Wc  (tf32 tensor cores) — independent of edges
    dim3 ggrid((N + GBM - 1) / GBM, HID / GBN);
    tf32_gemm_kernel<<<ggrid, 256>>>(h, Wc, x_dev, N);
    // 2. edge MLP + weighted degree
    fused_edge_kernel<<<(E + 255) / 256, 256>>>(attr, W1, b1, W2, b2, dst, w_dev, deg_dev, E);
    // 3. dinv + out = bc + dinv^2 * x
    finish_init_kernel<<<(N * 32 + 255) / 256, 256>>>(deg_dev, dinv_dev, x_dev, bc, out, N);
    // 4. edge scatter (profiled launch)
    long long tthreads = (long long)E * 32;
    agg_kernel<<<(unsigned)((tthreads + 255) / 256), 256>>>(src, dst, w_dev, dinv_dev, x_dev, out, E);
}

// round 9
// speedup vs baseline: 1.6520x; 1.0423x over previous
#include <cuda_runtime.h>
#include <cuda_bf16.h>
#include <cstdint>

#define HID 256
#define MAX_N 50000
#define MAX_E 800000

// ---------------- scratch (static __device__, no allocs) ----------------
__device__ float g_w[MAX_E];                 // per-edge sigmoid weight
__device__ float g_deg[MAX_N];               // weighted degree (excl. self loop)
__device__ float g_dinv[MAX_N];              // rsqrt(deg+1)
__device__ float g_x[(size_t)MAX_N * HID];   // h @ Wc

// ---------------- helpers ----------------
__device__ __forceinline__ float tanh_approx(float x) {
    float r;
    asm("tanh.approx.f32 %0, %1;" : "=f"(r) : "f"(x));
    return r;
}
__device__ __forceinline__ float to_tf32(float x) {
    uint32_t u;
    asm("cvt.rna.tf32.f32 %0, %1;" : "=r"(u) : "f"(x));
    return __uint_as_float(u);
}
__device__ __forceinline__ void mma_tf32(float4& c, const uint32_t* a, const uint32_t* b) {
    asm volatile(
        "mma.sync.aligned.m16n8k8.row.col.f32.tf32.tf32.f32 "
        "{%0,%1,%2,%3},{%4,%5,%6,%7},{%8,%9},{%0,%1,%2,%3};"
        : "+f"(c.x), "+f"(c.y), "+f"(c.z), "+f"(c.w)
        : "r"(a[0]), "r"(a[1]), "r"(a[2]), "r"(a[3]), "r"(b[0]), "r"(b[1]));
}
__device__ __forceinline__ void red_add_v4(float* addr, float4 v) {
    asm volatile("red.global.add.v4.f32 [%0], {%1,%2,%3,%4};"
                 :: "l"(addr), "f"(v.x), "f"(v.y), "f"(v.z), "f"(v.w)
                 : "memory");
}

// ---------------- kernel 1: TF32 GEMM  x = h @ Wc, reg-staged double buffer ----------------
// CTA tile 128x128, 8 warps, warp tile 32x64, BK=32, K=N=256 fixed.
#define GBM 128
#define GBN 128
#define GBK 32
#define TILESZ (GBK * (GBM + 4))      // floats per tile buffer (A and B identical)
#define GEMM_SMEM (4 * TILESZ * 4)    // bytes: A0,A1,B0,B1

__global__ __launch_bounds__(256) void tf32_gemm_kernel(const float* __restrict__ A,
                                                        const float* __restrict__ B,
                                                        float* __restrict__ C, int M) {
    extern __shared__ float sm[];
    float* Asm = sm;                 // [2][GBK][GBM+4]
    float* Bsm = sm + 2 * TILESZ;    // [2][GBK][GBN+4]

    int tid = threadIdx.x;
    int wid = tid >> 5;
    int lane = tid & 31;
    int g = lane >> 2;       // 0..7
    int tig = lane & 3;      // 0..3
    int bm = blockIdx.x * GBM;
    int bn = blockIdx.y * GBN;
    int wm = (wid >> 1) * 32;    // 0,32,64,96
    int wn = (wid & 1) * 64;     // 0,64
    bool full = (bm + GBM <= M);

    float4 acc[2][8];
#pragma unroll
    for (int mt = 0; mt < 2; mt++)
#pragma unroll
        for (int j = 0; j < 8; j++) acc[mt][j] = make_float4(0.f, 0.f, 0.f, 0.f);

    int arow = tid >> 3;          // 0..31
    int acol4 = tid & 7;          // 0..7
    int brow = tid >> 5;          // 0..7
    int bcol4 = tid & 31;         // 0..31

    float4 ra[4], rb[4];

#define LOAD_TILE(k0)                                                                   \
    {                                                                                   \
        _Pragma("unroll") for (int i = 0; i < 4; i++) {                                 \
            int gr = bm + arow + 32 * i;                                                \
            ra[i] = (full || gr < M)                                                    \
                ? *(const float4*)&A[(size_t)gr * HID + (k0) + acol4 * 4]               \
                : make_float4(0.f, 0.f, 0.f, 0.f);                                      \
        }                                                                               \
        _Pragma("unroll") for (int i = 0; i < 4; i++) {                                 \
            int kk = brow + 8 * i;                                                      \
            rb[i] = *(const float4*)&B[(size_t)((k0) + kk) * HID + bn + bcol4 * 4];     \
        }                                                                               \
    }

#define STORE_TILE(buf)                                                                 \
    {                                                                                   \
        float* ap = Asm + (buf) * TILESZ;                                               \
        float* bp = Bsm + (buf) * TILESZ;                                               \
        _Pragma("unroll") for (int i = 0; i < 4; i++) {                                 \
            int m = arow + 32 * i;                                                      \
            ap[(acol4 * 4 + 0) * (GBM + 4) + m] = to_tf32(ra[i].x);                     \
            ap[(acol4 * 4 + 1) * (GBM + 4) + m] = to_tf32(ra[i].y);                     \
            ap[(acol4 * 4 + 2) * (GBM + 4) + m] = to_tf32(ra[i].z);                     \
            ap[(acol4 * 4 + 3) * (GBM + 4) + m] = to_tf32(ra[i].w);                     \
        }                                                                               \
        _Pragma("unroll") for (int i = 0; i < 4; i++) {                                 \
            int kk = brow + 8 * i;                                                      \
            float4 v = rb[i];                                                           \
            v.x = to_tf32(v.x); v.y = to_tf32(v.y);                                     \
            v.z = to_tf32(v.z); v.w = to_tf32(v.w);                                     \
            *(float4*)&bp[kk * (GBN + 4) + bcol4 * 4] = v;                              \
        }                                                                               \
    }

#define COMPUTE_TILE(buf)                                                               \
    {                                                                                   \
        const float* ap = Asm + (buf) * TILESZ;                                         \
        const float* bp = Bsm + (buf) * TILESZ;                                         \
        _Pragma("unroll") for (int kr = 0; kr < GBK; kr += 8) {                         \
            uint32_t af[2][4];                                                          \
            uint32_t bf[8][2];                                                          \
            _Pragma("unroll") for (int mt = 0; mt < 2; mt++) {                          \
                int mb = wm + mt * 16 + g;                                              \
                af[mt][0] = __float_as_uint(ap[(kr + tig) * (GBM + 4) + mb]);           \
                af[mt][1] = __float_as_uint(ap[(kr + tig) * (GBM + 4) + mb + 8]);       \
                af[mt][2] = __float_as_uint(ap[(kr + tig + 4) * (GBM + 4) + mb]);       \
                af[mt][3] = __float_as_uint(ap[(kr + tig + 4) * (GBM + 4) + mb + 8]);   \
            }                                                                           \
            _Pragma("unroll") for (int j = 0; j < 8; j++) {                             \
                int nb = wn + j * 8 + g;                                                \
                bf[j][0] = __float_as_uint(bp[(kr + tig) * (GBN + 4) + nb]);            \
                bf[j][1] = __float_as_uint(bp[(kr + tig + 4) * (GBN + 4) + nb]);        \
            }                                                                           \
            _Pragma("unroll") for (int mt = 0; mt < 2; mt++)                            \
                _Pragma("unroll") for (int j = 0; j < 8; j++)                           \
                    mma_tf32(acc[mt][j], af[mt], bf[j]);                                \
        }                                                                               \
    }

    // prologue: tile 0
    LOAD_TILE(0);
    STORE_TILE(0);
    __syncthreads();

    int buf = 0;
#pragma unroll
    for (int t = 1; t < HID / GBK; t++) {
        LOAD_TILE(t * GBK);       // prefetch next tile into registers
        COMPUTE_TILE(buf);        // compute current tile
        STORE_TILE(buf ^ 1);      // stage next tile into the other buffer
        __syncthreads();
        buf ^= 1;
    }
    COMPUTE_TILE(buf);

    // epilogue
#pragma unroll
    for (int mt = 0; mt < 2; mt++) {
        int row0 = bm + wm + mt * 16 + g;
        int row1 = row0 + 8;
#pragma unroll
        for (int j = 0; j < 8; j++) {
            int col = bn + wn + j * 8 + tig * 2;
            if (row0 < M) *(float2*)&C[(size_t)row0 * HID + col] = make_float2(acc[mt][j].x, acc[mt][j].y);
            if (row1 < M) *(float2*)&C[(size_t)row1 * HID + col] = make_float2(acc[mt][j].z, acc[mt][j].w);
        }
    }
#undef LOAD_TILE
#undef STORE_TILE
#undef COMPUTE_TILE
}

// ---------------- kernel 2: fused edge MLP -> w, + weighted degree ----------------
__global__ __launch_bounds__(256) void fused_edge_kernel(const float* __restrict__ attr,
                                const float* __restrict__ W1,
                                const float* __restrict__ b1,
                                const float* __restrict__ W2,
                                const float* __restrict__ b2,
                                const int* __restrict__ dst,
                                float* __restrict__ w,
                                float* __restrict__ deg, int E) {
    __shared__ float4 sA[128];   // {W1[0][j], W1[1][j], W1[2][j], b1[j]}
    __shared__ float  sV[128];   // W2[j]
    __shared__ float  sAttr[768];
    int tid = threadIdx.x;
    if (tid < 128) {
        sA[tid] = make_float4(W1[tid], W1[128 + tid], W1[256 + tid], b1[tid]);
        sV[tid] = W2[tid];
    }
    // coalesced attr staging: 768 floats = 192 float4 per block
    long base3 = (long)blockIdx.x * 768;
    if (base3 + 768 <= (long)E * 3) {
        if (tid < 192)
            ((float4*)sAttr)[tid] = ((const float4*)(attr + base3))[tid];
    } else {
        for (int i = tid; i < 768; i += 256) {
            long gi = base3 + i;
            sAttr[i] = (gi < (long)E * 3) ? attr[gi] : 0.0f;
        }
    }
    __syncthreads();
    int e = blockIdx.x * blockDim.x + tid;
    if (e >= E) return;
    float a0 = sAttr[tid * 3 + 0];
    float a1 = sAttr[tid * 3 + 1];
    float a2 = sAttr[tid * 3 + 2];
    float acc = b2[0];
#pragma unroll 8
    for (int j = 0; j < 128; j++) {
        float4 c = sA[j];
        float z = fmaf(a0, c.x, fmaf(a1, c.y, fmaf(a2, c.z, c.w)));
        float t = tanh_approx(0.5f * z);            // silu via tanh
        acc = fmaf(0.5f * z * (1.0f + t), sV[j], acc);
    }
    float wv = fmaf(0.5f, tanh_approx(0.5f * acc), 0.5f);  // sigmoid
    w[e] = wv;
    atomicAdd(&deg[dst[e]], wv);
}

// ---------------- kernel 3: dinv + out init (bias + self loop), 1 warp/node ----------------
__global__ __launch_bounds__(256) void finish_init_kernel(const float* __restrict__ deg,
                                                          float* __restrict__ dinv,
                                                          const float* __restrict__ x,
                                                          const float* __restrict__ bc,
                                                          float* __restrict__ out, int N) {
    int node = (blockIdx.x * blockDim.x + threadIdx.x) >> 5;
    int lane = threadIdx.x & 31;
    if (node >= N) return;
    float d = rsqrtf(deg[node] + 1.0f);   // + self loop weight
    if (lane == 0) dinv[node] = d;
    float s = d * d;
    const float4* x4 = (const float4*)x;
    const float4* bc4 = (const float4*)bc;
    float4* out4 = (float4*)out;
    size_t base = (size_t)node * 64;
#pragma unroll
    for (int i = 0; i < 2; i++) {
        int k = lane + i * 32;
        float4 xv = x4[base + k];
        float4 bv = bc4[k];
        float4 o;
        o.x = fmaf(s, xv.x, bv.x);
        o.y = fmaf(s, xv.y, bv.y);
        o.z = fmaf(s, xv.z, bv.z);
        o.w = fmaf(s, xv.w, bv.w);
        out4[base + k] = o;
    }
}

// ---------------- kernel 4: edge aggregation (1 warp / edge, red.v4) ----------------
__global__ __launch_bounds__(256) void agg_kernel(const int* __restrict__ src,
                                                  const int* __restrict__ dst,
                                                  const float* __restrict__ w,
                                                  const float* __restrict__ dinv,
                                                  const float* __restrict__ x,
                                                  float* __restrict__ out, int E) {
    int warp = (blockIdx.x * blockDim.x + threadIdx.x) >> 5;
    int lane = threadIdx.x & 31;
    if (warp >= E) return;
    int r = src[warp];
    int c = dst[warp];
    float nrm = w[warp] * dinv[r] * dinv[c];
    const float4* xr = (const float4*)(x + (size_t)r * HID);
    float* oc = out + (size_t)c * HID;
#pragma unroll
    for (int i = 0; i < 2; i++) {
        int k = lane + i * 32;               // 0..63 float4 chunks
        float4 v = xr[k];
        v.x *= nrm; v.y *= nrm; v.z *= nrm; v.w *= nrm;
        red_add_v4(oc + k * 4, v);
    }
}

// ---------------- launcher ----------------
extern "C" void kernel_launch(void* const* d_in, const int* in_sizes, int n_in,
                              void* d_out, int out_size) {
    const float* h    = (const float*)d_in[0];
    const int*   eidx = (const int*)d_in[1];     // JAX int64 -> int32 (x64 disabled)
    const float* attr = (const float*)d_in[2];
    const float* W1   = (const float*)d_in[3];
    const float* b1   = (const float*)d_in[4];
    const float* W2   = (const float*)d_in[5];
    const float* b2   = (const float*)d_in[6];
    const float* Wc   = (const float*)d_in[7];
    const float* bc   = (const float*)d_in[8];
    float* out = (float*)d_out;

    int N = in_sizes[0] / HID;       // 50000
    int E = in_sizes[2] / 3;         // 800000
    const int* src = eidx;           // edge_index[0] (sources)
    const int* dst = eidx + E;       // edge_index[1] (targets)

    float* w_dev;    cudaGetSymbolAddress((void**)&w_dev, g_w);
    float* deg_dev;  cudaGetSymbolAddress((void**)&deg_dev, g_deg);
    float* dinv_dev; cudaGetSymbolAddress((void**)&dinv_dev, g_dinv);
    float* x_dev;    cudaGetSymbolAddress((void**)&x_dev, g_x);

    // one-time side stream / events / smem attribute (host-side only, no device mem)
    static cudaStream_t s_side = nullptr;
    static cudaEvent_t s_fork = nullptr, s_join = nullptr;
    if (!s_side) {
        cudaStreamCreateWithFlags(&s_side, cudaStreamNonBlocking);
        cudaEventCreateWithFlags(&s_fork, cudaEventDisableTiming);
        cudaEventCreateWithFlags(&s_join, cudaEventDisableTiming);
        cudaFuncSetAttribute(tf32_gemm_kernel,
                             cudaFuncAttributeMaxDynamicSharedMemorySize, GEMM_SMEM);
    }

    // fork: GEMM on side stream, edge pipeline on main stream
    cudaEventRecord(s_fork, 0);
    cudaStreamWaitEvent(s_side, s_fork, 0);

    dim3 ggrid((N + GBM - 1) / GBM, HID / GBN);
    tf32_gemm_kernel<<<ggrid, 256, GEMM_SMEM, s_side>>>(h, Wc, x_dev, N);
    cudaEventRecord(s_join, s_side);

    cudaMemsetAsync(deg_dev, 0, (size_t)N * sizeof(float));
    fused_edge_kernel<<<(E + 255) / 256, 256>>>(attr, W1, b1, W2, b2, dst, w_dev, deg_dev, E);

    // join
    cudaStreamWaitEvent(0, s_join, 0);

    // dinv + out = bc + dinv^2 * x
    finish_init_kernel<<<(N * 32 + 255) / 256, 256>>>(deg_dev, dinv_dev, x_dev, bc, out, N);
    // edge scatter
    long long tthreads = (long long)E * 32;
    agg_kernel<<<(unsigned)((tthreads + 255) / 256), 256>>>(src, dst, w_dev, dinv_dev, x_dev, out, E);
}